// round 2
// baseline (speedup 1.0000x reference)
#include <cuda_runtime.h>
#include <cuda_bf16.h>

// CorrectedHistogramLoss: triangular soft-histogram (R=64) of clip(sim) and
// clip(dissim1), cumsum + dots -> scalar. dissim2/margin/anchor_swap unused.
//
// R2: single fused kernel. Packed-u64 fixed-point shared atomics for the
// histogram (one 64-bit ATOMS per element per histogram, deterministic),
// per-block partials to a __device__ scratch array, last-block (atomic
// counter) does the cross-block reduction + parallel scan + dot products.

#define NBLK 152      // 1 block per SM
#define NTHR 512
#define NWARP (NTHR / 32)
#define RBINS 64
#define FSCALE 2097152.0f   // 2^21

__device__ float g_part[NBLK][2 * RBINS];
__device__ unsigned int g_count;   // zero-init; reset to 0 by last block each run

__device__ __forceinline__ void acc_val(unsigned long long* h, float x) {
    float xc = fminf(fmaxf(x, -1.0f), 1.0f);
    float u  = (xc + 1.0f) * 31.5f;      // (x+1)/LAM, LAM = 2/63
    float fl = floorf(u);
    float w  = u - fl;
    int   f  = (int)fl;
    if (w > 0.0f && f < 63) {            // w==0 contributes nothing (strict ineq. in ref)
        unsigned int wa = __float2uint_rn((1.0f - w) * FSCALE);  // bin f
        unsigned int wb = __float2uint_rn(w * FSCALE);           // bin f+1
        unsigned long long pk = (unsigned long long)wa | ((unsigned long long)wb << 32);
        // slots 0..31: even-pair copy (bins 2k | 2k+1), slots 32..63: odd-pair (2k+1 | 2k+2)
        int slot = (f & 1) ? (32 + ((f - 1) >> 1)) : (f >> 1);
        atomicAdd(h + slot, pk);
    }
}

__global__ void __launch_bounds__(NTHR)
fused_kernel(const float* __restrict__ sim, const float* __restrict__ dis,
             float* __restrict__ out, int n) {
    __shared__ unsigned long long sh[NWARP][2][64];   // 16 KB
    __shared__ float red[4][2 * RBINS];
    __shared__ float hist[2 * RBINS];
    __shared__ float horg[2 * RBINS];
    __shared__ float wacc[2];
    __shared__ int   is_last;

    int tid = threadIdx.x;
    int wp  = tid >> 5;

    for (int i = tid; i < NWARP * 2 * 64; i += NTHR)
        ((unsigned long long*)sh)[i] = 0ULL;
    __syncthreads();

    unsigned long long* h0 = sh[wp][0];
    unsigned long long* h1 = sh[wp][1];

    int nv = n >> 2;
    int stride = gridDim.x * blockDim.x;
    const float4* s4 = (const float4*)sim;
    const float4* d4 = (const float4*)dis;

    for (int i = blockIdx.x * blockDim.x + tid; i < nv; i += stride) {
        float4 a = s4[i];
        float4 b = d4[i];
        acc_val(h0, a.x); acc_val(h0, a.y); acc_val(h0, a.z); acc_val(h0, a.w);
        acc_val(h1, b.x); acc_val(h1, b.y); acc_val(h1, b.z); acc_val(h1, b.w);
    }
    if (blockIdx.x == 0 && tid == 0) {   // scalar tail (n not multiple of 4)
        for (int i = nv << 2; i < n; i++) { acc_val(h0, sim[i]); acc_val(h1, dis[i]); }
    }
    __syncthreads();

    // decode packed pairs, reduce warps -> per-block partial (128 floats)
    if (tid < 2 * RBINS) {
        int h = tid >> 6;
        int r = tid & 63;
        unsigned long long sum = 0ULL;
        #pragma unroll
        for (int w = 0; w < NWARP; w++) {
            unsigned long long e = sh[w][h][r >> 1];                  // even-pair copy
            sum += (r & 1) ? (e >> 32) : (e & 0xffffffffULL);
            if (r >= 1 && r <= 62) {                                   // odd-pair copy
                int k = (r & 1) ? ((r - 1) >> 1) : ((r >> 1) - 1);
                unsigned long long o = sh[w][h][32 + k];
                sum += (r & 1) ? (o & 0xffffffffULL) : (o >> 32);
            }
        }
        g_part[blockIdx.x][tid] = (float)sum;
    }
    __threadfence();
    __syncthreads();

    if (tid == 0)
        is_last = (atomicAdd(&g_count, 1u) == (unsigned)(gridDim.x - 1));
    __syncthreads();
    if (!is_last) return;
    __threadfence();   // acquire: g_part writes from all blocks visible

    // ---- last block: cross-block reduction (512 threads, 4 per bin) ----
    {
        int bin = tid & 127;
        int j   = tid >> 7;          // 0..3
        float s = 0.0f;
        for (int b = j; b < NBLK; b += 4) s += g_part[b][bin];
        red[j][bin] = s;
    }
    __syncthreads();

    float inv = 1.0f / ((float)n * FSCALE);
    if (tid < 2 * RBINS) {
        float t = (red[0][tid] + red[1][tid] + red[2][tid] + red[3][tid]) * inv;
        horg[tid] = t;
        hist[tid] = t;
    }
    __syncthreads();

    // ---- inclusive prefix scan within each 64-bin segment (Hillis-Steele) ----
    #pragma unroll
    for (int off = 1; off < RBINS; off <<= 1) {
        float v = 0.0f, add = 0.0f;
        if (tid < 2 * RBINS) {
            v = hist[tid];
            if ((tid & 63) >= off) add = hist[tid - off];
        }
        __syncthreads();
        if (tid < 2 * RBINS) hist[tid] = v + add;
        __syncthreads();
    }

    // ---- dot products + final scalar ----
    const float q = 0.9f, Pp = 0.1f;
    float term = 0.0f;
    if (tid < RBINS) {
        float hpc = hist[tid];
        float hmc = hist[RBINS + tid];
        float hp  = horg[tid];
        float hm  = horg[RBINS + tid];
        term = q * q * hpc * hm - q * Pp * hpc * hp - q * Pp * hmc * hm + Pp * Pp * hmc * hp;
    }
    // reduce over 64 threads (warps 0 and 1)
    #pragma unroll
    for (int off = 16; off > 0; off >>= 1)
        term += __shfl_down_sync(0xffffffffu, term, off);
    if (tid < RBINS && (tid & 31) == 0) wacc[tid >> 5] = term;
    __syncthreads();
    if (tid == 0) {
        float num = wacc[0] + wacc[1];
        out[0] = num / (1.0f - 4.0f * Pp + 4.0f * Pp * Pp);   // / 0.64
        g_count = 0;   // reset for next graph replay
    }
}

extern "C" void kernel_launch(void* const* d_in, const int* in_sizes, int n_in,
                              void* d_out, int out_size) {
    const float* sim = (const float*)d_in[0];
    const float* dis = (const float*)d_in[1];   // dissim1; dissim2/margin/anchor_swap unused
    int n = in_sizes[0];
    fused_kernel<<<NBLK, NTHR>>>(sim, dis, (float*)d_out, n);
}

// round 3
// speedup vs baseline: 1.2635x; 1.2635x over previous
#include <cuda_runtime.h>
#include <cuda_bf16.h>

// CorrectedHistogramLoss: triangular soft-histogram (R=64) of clip(sim) and
// clip(dissim1), cumsum + dots -> scalar. dissim2/margin/anchor_swap unused.
//
// R3: single fused kernel. Packed-u64 fixed-point shared atomics (one 64-bit
// ATOMS per element per histogram). Each block folds its counts directly into
// a 128-entry global u64 accumulator (deterministic integer atomics) — no
// per-block partial array, no serial L2 read chain. Last block loads 128 u64,
// shuffle-scans, dots, writes scalar, resets state for graph replay.

#define NBLK 304      // 2 waves on 152 SMs (R1-proven hist config)
#define NTHR 256
#define NWARP (NTHR / 32)
#define RBINS 64
#define FSCALE 2097152.0f   // 2^21

__device__ unsigned long long g_hist[2 * RBINS];  // zero-init; reset by last block
__device__ unsigned int g_count;                  // zero-init; reset by last block

__device__ __forceinline__ void acc_val(unsigned long long* h, float x) {
    float xc = fminf(fmaxf(x, -1.0f), 1.0f);
    float u  = (xc + 1.0f) * 31.5f;      // (x+1)/LAM, LAM = 2/63
    float fl = floorf(u);
    float w  = u - fl;
    int   f  = (int)fl;
    if (w > 0.0f && f < 63) {            // w==0 contributes nothing (strict ineq. in ref)
        unsigned int wa = __float2uint_rn((1.0f - w) * FSCALE);  // bin f
        unsigned int wb = __float2uint_rn(w * FSCALE);           // bin f+1
        unsigned long long pk = (unsigned long long)wa | ((unsigned long long)wb << 32);
        // slots 0..31: even-pair copy (bins 2k | 2k+1), slots 32..63: odd-pair (2k+1 | 2k+2)
        int slot = (f & 1) ? (32 + ((f - 1) >> 1)) : (f >> 1);
        atomicAdd(h + slot, pk);
    }
}

__global__ void __launch_bounds__(NTHR)
fused_kernel(const float* __restrict__ sim, const float* __restrict__ dis,
             float* __restrict__ out, int n) {
    __shared__ unsigned long long sh[NWARP][2][64];   // 8 KB
    __shared__ float sc[2 * RBINS];     // scanned hist
    __shared__ float so[2 * RBINS];     // original hist
    __shared__ float warptot[4];
    __shared__ float acc2[2];
    __shared__ int   is_last;

    int tid  = threadIdx.x;
    int wp   = tid >> 5;
    int lane = tid & 31;

    for (int i = tid; i < NWARP * 2 * 64; i += NTHR)
        ((unsigned long long*)sh)[i] = 0ULL;
    __syncthreads();

    unsigned long long* h0 = sh[wp][0];
    unsigned long long* h1 = sh[wp][1];

    int nv = n >> 2;
    int stride = gridDim.x * blockDim.x;
    const float4* s4 = (const float4*)sim;
    const float4* d4 = (const float4*)dis;

    for (int i = blockIdx.x * blockDim.x + tid; i < nv; i += stride) {
        float4 a = s4[i];
        float4 b = d4[i];
        acc_val(h0, a.x); acc_val(h0, a.y); acc_val(h0, a.z); acc_val(h0, a.w);
        acc_val(h1, b.x); acc_val(h1, b.y); acc_val(h1, b.z); acc_val(h1, b.w);
    }
    if (blockIdx.x == 0 && tid == 0) {   // scalar tail (n not multiple of 4)
        for (int i = nv << 2; i < n; i++) { acc_val(h0, sim[i]); acc_val(h1, dis[i]); }
    }
    __syncthreads();

    // decode packed pairs, reduce warps -> one integer per bin, fold into global
    if (tid < 2 * RBINS) {
        int h = tid >> 6;
        int r = tid & 63;
        unsigned long long sum = 0ULL;
        #pragma unroll
        for (int w = 0; w < NWARP; w++) {
            unsigned long long e = sh[w][h][r >> 1];                  // even-pair copy
            sum += (r & 1) ? (e >> 32) : (e & 0xffffffffULL);
            if (r >= 1 && r <= 62) {                                   // odd-pair copy
                int k = (r & 1) ? ((r - 1) >> 1) : ((r >> 1) - 1);
                unsigned long long o = sh[w][h][32 + k];
                sum += (r & 1) ? (o & 0xffffffffULL) : (o >> 32);
            }
        }
        atomicAdd(&g_hist[tid], sum);   // deterministic integer accumulation
        __threadfence();                // order g_hist adds before g_count bump
    }
    __syncthreads();

    if (tid == 0)
        is_last = (atomicAdd(&g_count, 1u) == (unsigned)(gridDim.x - 1));
    __syncthreads();
    if (!is_last) return;
    __threadfence();   // acquire: all blocks' g_hist adds visible

    // ---- last block epilogue: 128 u64 loads + shuffle scan + dots ----
    float v = 0.0f, x = 0.0f;
    float inv = 1.0f / ((float)n * FSCALE);
    if (tid < 2 * RBINS) {               // warps 0..3, full warps active
        v = (float)g_hist[tid] * inv;
        x = v;
        #pragma unroll
        for (int off = 1; off < 32; off <<= 1) {   // warp inclusive scan
            float y = __shfl_up_sync(0xffffffffu, x, off);
            if (lane >= off) x += y;
        }
        if (lane == 31) warptot[wp] = x;
    }
    __syncthreads();
    if (tid < 2 * RBINS) {
        if (wp == 1) x += warptot[0];     // second half of hist_plus segment
        if (wp == 3) x += warptot[2];     // second half of hist_minus segment
        sc[tid] = x;
        so[tid] = v;
    }
    __syncthreads();

    const float q = 0.9f, Pp = 0.1f;
    float term = 0.0f;
    if (tid < RBINS) {
        float hpc = sc[tid];
        float hmc = sc[RBINS + tid];
        float hp  = so[tid];
        float hm  = so[RBINS + tid];
        term = q * q * hpc * hm - q * Pp * hpc * hp - q * Pp * hmc * hm + Pp * Pp * hmc * hp;
    }
    #pragma unroll
    for (int off = 16; off > 0; off >>= 1)
        term += __shfl_down_sync(0xffffffffu, term, off);
    if (tid == 0)  acc2[0] = term;
    if (tid == 32) acc2[1] = term;
    __syncthreads();

    if (tid < 2 * RBINS) g_hist[tid] = 0ULL;   // reset for next graph replay
    if (tid == 0) {
        out[0] = (acc2[0] + acc2[1]) / (1.0f - 4.0f * Pp + 4.0f * Pp * Pp);  // /0.64
        g_count = 0;
    }
}

extern "C" void kernel_launch(void* const* d_in, const int* in_sizes, int n_in,
                              void* d_out, int out_size) {
    const float* sim = (const float*)d_in[0];
    const float* dis = (const float*)d_in[1];   // dissim1; dissim2/margin/anchor_swap unused
    int n = in_sizes[0];
    fused_kernel<<<NBLK, NTHR>>>(sim, dis, (float*)d_out, n);
}